// round 1
// baseline (speedup 1.0000x reference)
#include <cuda_runtime.h>
#include <math_constants.h>

#define BB    4
#define NN    2048
#define DIMC  768
#define HEADS 12
#define HD    64
#define MTOK  (BB * NN)   /* 8192 tokens */

// Scratch (allocation-free rule: __device__ globals)
__device__ float g_qkv[(size_t)MTOK * 3 * DIMC];   // [8192, 2304]
__device__ float g_att[(size_t)MTOK * DIMC];       // [8192, 768]

// ---------------------------------------------------------------------------
// Generic SGEMM + bias: C[M,N] = A[M,K] @ B[K,N] + bias[N]
// 128x128 block tile, K-tile 8, 256 threads, 8x8 per-thread microtile
// (split as 2x2 of 4x4 so smem fragment loads are float4 with <=2-way conflicts)
// All of M,N divisible by 128 and K by 8 for our shapes -> no bounds checks.
// ---------------------------------------------------------------------------
__global__ __launch_bounds__(256, 2)
void sgemm_bias(const float* __restrict__ A, const float* __restrict__ B,
                const float* __restrict__ bias, float* __restrict__ C,
                int M, int N, int K)
{
    __shared__ float As[8][132];   // As[k][m], padded
    __shared__ float Bs[8][132];   // Bs[k][n], padded

    const int tid = threadIdx.x;
    const int tx  = tid & 15;      // column group
    const int ty  = tid >> 4;      // row group
    const int bm  = blockIdx.y * 128;
    const int bn  = blockIdx.x * 128;

    // global->smem load indices
    const int a_row = tid >> 1;          // 0..127
    const int a_k   = (tid & 1) * 4;     // 0 or 4
    const int b_k   = tid >> 5;          // 0..7
    const int b_col = (tid & 31) * 4;    // 0..124

    const float* Ap = A + (size_t)(bm + a_row) * K + a_k;
    const float* Bp = B + (size_t)b_k * N + bn + b_col;

    float acc[8][8];
#pragma unroll
    for (int i = 0; i < 8; i++)
#pragma unroll
        for (int j = 0; j < 8; j++) acc[i][j] = 0.0f;

    for (int k0 = 0; k0 < K; k0 += 8) {
        float4 av = *(const float4*)(Ap + k0);
        float4 bv = *(const float4*)(Bp + (size_t)k0 * N);
        __syncthreads();  // previous tile's compute done before overwrite
        As[a_k + 0][a_row] = av.x;
        As[a_k + 1][a_row] = av.y;
        As[a_k + 2][a_row] = av.z;
        As[a_k + 3][a_row] = av.w;
        *(float4*)&Bs[b_k][b_col] = bv;
        __syncthreads();

#pragma unroll
        for (int kk = 0; kk < 8; kk++) {
            float ar[8], br[8];
            *(float4*)&ar[0] = *(const float4*)&As[kk][ty * 4];
            *(float4*)&ar[4] = *(const float4*)&As[kk][64 + ty * 4];
            *(float4*)&br[0] = *(const float4*)&Bs[kk][tx * 4];
            *(float4*)&br[4] = *(const float4*)&Bs[kk][64 + tx * 4];
#pragma unroll
            for (int i = 0; i < 8; i++)
#pragma unroll
                for (int j = 0; j < 8; j++)
                    acc[i][j] = fmaf(ar[i], br[j], acc[i][j]);
        }
    }

    // epilogue: bias add + float4 stores
#pragma unroll
    for (int i = 0; i < 8; i++) {
        const int row = bm + ((i < 4) ? (ty * 4 + i) : (64 + ty * 4 + (i - 4)));
#pragma unroll
        for (int jn = 0; jn < 2; jn++) {
            const int col = bn + jn * 64 + tx * 4;
            float4 o;
            o.x = acc[i][jn * 4 + 0] + bias[col + 0];
            o.y = acc[i][jn * 4 + 1] + bias[col + 1];
            o.z = acc[i][jn * 4 + 2] + bias[col + 2];
            o.w = acc[i][jn * 4 + 3] + bias[col + 3];
            *(float4*)(C + (size_t)row * N + col) = o;
        }
    }
}

// ---------------------------------------------------------------------------
// Flash attention (fp32, full/non-causal), head_dim = 64.
// One block per (batch, head, 64-query tile). 256 threads.
// Thread (lr = tid/16, lc = tid%16) owns rows r0=4*lr, cols c0=4*lc (4x4 tiles).
// Row reductions: 16 consecutive lanes -> intra-warp shfl_xor butterfly.
// Q,K kept d-major (transposed) in smem; P written transposed for the O phase.
// ---------------------------------------------------------------------------
__global__ __launch_bounds__(256, 2)
void attn_kernel(const float* __restrict__ qkv, float* __restrict__ outp)
{
    extern __shared__ float smx[];
    float (*Qs)[68] = (float(*)[68])(smx);             // Qs[d][r]
    float (*Ks)[68] = (float(*)[68])(smx + 64 * 68);   // Ks[d][c]
    float (*Vs)[68] = (float(*)[68])(smx + 2 * 64 * 68); // Vs[k][d]
    float (*Ps)[68] = (float(*)[68])(smx + 3 * 64 * 68); // Ps[k][r]

    const int tid = threadIdx.x;
    const int qt  = blockIdx.x & 31;                 // 32 q-tiles
    const int h   = (blockIdx.x >> 5) % HEADS;
    const int b   = blockIdx.x / (32 * HEADS);
    const int q0  = qt * 64;

    const int lr = tid >> 4;       // 0..15
    const int lc = tid & 15;       // 0..15
    const int r0 = lr * 4;
    const int c0 = lc * 4;

    const float scale = 0.125f;    // 64^-0.5

    // Load Q tile transposed (and pre-scale)
    {
        const int d0 = lc * 4;
#pragma unroll
        for (int p = 0; p < 4; p++) {
            const int r = p * 16 + lr;
            const float* qp = qkv + (size_t)(b * NN + q0 + r) * (3 * DIMC) + h * HD + d0;
            float4 v = *(const float4*)qp;
            Qs[d0 + 0][r] = v.x * scale;
            Qs[d0 + 1][r] = v.y * scale;
            Qs[d0 + 2][r] = v.z * scale;
            Qs[d0 + 3][r] = v.w * scale;
        }
    }

    float m_[4], l_[4], o_[4][4];
#pragma unroll
    for (int i = 0; i < 4; i++) {
        m_[i] = -CUDART_INF_F;
        l_[i] = 0.0f;
#pragma unroll
        for (int j = 0; j < 4; j++) o_[i][j] = 0.0f;
    }

    for (int kt = 0; kt < NN / 64; kt++) {
        __syncthreads();  // previous O-phase reads done; also covers initial Q store
        // Load K (transposed) and V (natural) tiles
        {
            const int d0 = lc * 4;
#pragma unroll
            for (int p = 0; p < 4; p++) {
                const int r = p * 16 + lr;
                const float* base = qkv + (size_t)(b * NN + kt * 64 + r) * (3 * DIMC) + h * HD + d0;
                float4 kv = *(const float4*)(base + DIMC);
                Ks[d0 + 0][r] = kv.x;
                Ks[d0 + 1][r] = kv.y;
                Ks[d0 + 2][r] = kv.z;
                Ks[d0 + 3][r] = kv.w;
                float4 vv = *(const float4*)(base + 2 * DIMC);
                *(float4*)&Vs[r][d0] = vv;
            }
        }
        __syncthreads();

        // S = Q K^T (scaled)
        float s[4][4];
#pragma unroll
        for (int i = 0; i < 4; i++)
#pragma unroll
            for (int j = 0; j < 4; j++) s[i][j] = 0.0f;

#pragma unroll 16
        for (int d = 0; d < 64; d++) {
            float4 qa = *(const float4*)&Qs[d][r0];
            float4 kb = *(const float4*)&Ks[d][c0];
            float qv[4] = {qa.x, qa.y, qa.z, qa.w};
            float kv[4] = {kb.x, kb.y, kb.z, kb.w};
#pragma unroll
            for (int i = 0; i < 4; i++)
#pragma unroll
                for (int j = 0; j < 4; j++)
                    s[i][j] = fmaf(qv[i], kv[j], s[i][j]);
        }

        // Online softmax update per owned row
#pragma unroll
        for (int i = 0; i < 4; i++) {
            float mx = fmaxf(fmaxf(s[i][0], s[i][1]), fmaxf(s[i][2], s[i][3]));
#pragma unroll
            for (int off = 1; off < 16; off <<= 1)
                mx = fmaxf(mx, __shfl_xor_sync(0xffffffffu, mx, off));
            const float newm = fmaxf(m_[i], mx);
            const float corr = __expf(m_[i] - newm);
            const float p0 = __expf(s[i][0] - newm);
            const float p1 = __expf(s[i][1] - newm);
            const float p2 = __expf(s[i][2] - newm);
            const float p3 = __expf(s[i][3] - newm);
            float rs = (p0 + p1) + (p2 + p3);
#pragma unroll
            for (int off = 1; off < 16; off <<= 1)
                rs += __shfl_xor_sync(0xffffffffu, rs, off);
            l_[i] = l_[i] * corr + rs;
            m_[i] = newm;
#pragma unroll
            for (int j = 0; j < 4; j++) o_[i][j] *= corr;
            Ps[c0 + 0][r0 + i] = p0;
            Ps[c0 + 1][r0 + i] = p1;
            Ps[c0 + 2][r0 + i] = p2;
            Ps[c0 + 3][r0 + i] = p3;
        }
        __syncthreads();  // P visible to all row readers

        // O += P @ V
#pragma unroll 16
        for (int k = 0; k < 64; k++) {
            float4 pa = *(const float4*)&Ps[k][r0];
            float4 vb = *(const float4*)&Vs[k][c0];
            float pv[4] = {pa.x, pa.y, pa.z, pa.w};
            float vv[4] = {vb.x, vb.y, vb.z, vb.w};
#pragma unroll
            for (int i = 0; i < 4; i++)
#pragma unroll
                for (int j = 0; j < 4; j++)
                    o_[i][j] = fmaf(pv[i], vv[j], o_[i][j]);
        }
    }

    // epilogue: normalize and store into [B,N, H*D] layout (ready for proj GEMM)
#pragma unroll
    for (int i = 0; i < 4; i++) {
        const float inv = 1.0f / l_[i];
        float4 ov;
        ov.x = o_[i][0] * inv;
        ov.y = o_[i][1] * inv;
        ov.z = o_[i][2] * inv;
        ov.w = o_[i][3] * inv;
        const int row = b * NN + q0 + r0 + i;
        *(float4*)(outp + (size_t)row * DIMC + h * HD + c0) = ov;
    }
}

// ---------------------------------------------------------------------------
extern "C" void kernel_launch(void* const* d_in, const int* in_sizes, int n_in,
                              void* d_out, int out_size)
{
    const float* x      = (const float*)d_in[0];
    const float* w_qkv  = (const float*)d_in[1];
    const float* b_qkv  = (const float*)d_in[2];
    const float* w_proj = (const float*)d_in[3];
    const float* b_proj = (const float*)d_in[4];
    float* out = (float*)d_out;

    float *qkv_s = nullptr, *att_s = nullptr;
    cudaGetSymbolAddress((void**)&qkv_s, g_qkv);
    cudaGetSymbolAddress((void**)&att_s, g_att);

    // 1) QKV GEMM: [8192,768] @ [768,2304] + bias
    {
        dim3 grid((3 * DIMC) / 128, MTOK / 128);
        sgemm_bias<<<grid, 256>>>(x, w_qkv, b_qkv, qkv_s, MTOK, 3 * DIMC, DIMC);
    }

    // 2) Flash attention: 4 * 12 * 32 blocks
    {
        const int smem = 4 * 64 * 68 * (int)sizeof(float);  // 69632 B
        cudaFuncSetAttribute(attn_kernel,
                             cudaFuncAttributeMaxDynamicSharedMemorySize, smem);
        attn_kernel<<<BB * HEADS * 32, 256, smem>>>(qkv_s, att_s);
    }

    // 3) Projection GEMM: [8192,768] @ [768,768] + bias
    {
        dim3 grid(DIMC / 128, MTOK / 128);
        sgemm_bias<<<grid, 256>>>(att_s, w_proj, b_proj, out, MTOK, DIMC, DIMC);
    }
}

// round 5
// speedup vs baseline: 2.2359x; 2.2359x over previous
#include <cuda_runtime.h>
#include <math_constants.h>
#include <cstdint>

#define BB    4
#define NN    2048
#define DIMC  768
#define HEADS 12
#define HD    64
#define MTOK  (BB * NN)   /* 8192 tokens */

// Scratch (allocation-free rule: __device__ globals)
__device__ float g_qkv[(size_t)MTOK * 3 * DIMC];   // [8192, 2304]
__device__ float g_att[(size_t)MTOK * DIMC];       // [8192, 768]

// ---------------------------------------------------------------------------
// tf32 helpers (sm_80+ PTX only — NO 'a'-gated instructions)
// ---------------------------------------------------------------------------
__device__ __forceinline__ uint32_t f2tf(float x) {
    uint32_t r;
    asm("cvt.rna.tf32.f32 %0, %1;" : "=r"(r) : "f"(x));
    return r;
}

// D += A @ B ; m16n8k8 tf32, fp32 accumulate.
// A frag: a0=(g,t) a1=(g+8,t) a2=(g,t+4) a3=(g+8,t+4); g=lane>>2, t=lane&3
// B frag: b0=(k=t, n=g) b1=(k=t+4, n=g)
// C frag: c0=(g,2t) c1=(g,2t+1) c2=(g+8,2t) c3=(g+8,2t+1)
__device__ __forceinline__ void mma_tf32(float* d, const uint32_t* a, const uint32_t* b) {
    asm volatile(
        "mma.sync.aligned.m16n8k8.row.col.f32.tf32.tf32.f32 "
        "{%0,%1,%2,%3}, {%4,%5,%6,%7}, {%8,%9}, {%0,%1,%2,%3};"
        : "+f"(d[0]), "+f"(d[1]), "+f"(d[2]), "+f"(d[3])
        : "r"(a[0]), "r"(a[1]), "r"(a[2]), "r"(a[3]), "r"(b[0]), "r"(b[1]));
}

// Within-8 column permutation so that (c, c+4) land adjacent -> LDS.64 frags.
// p(j) = 2*(j&3) + (j>>2), applied per 8-wide k-block.
__device__ __forceinline__ int pcol(int c) {
    return (c & ~7) + ((c & 3) << 1) + ((c >> 2) & 1);
}

// ===========================================================================
// GEMM: C[M,N] = A[M,K] @ B[K,N] + bias[N]   (tf32 mma.sync)
// 128x128 tile, BK=32, 256 threads (8 warps, 4x2 layout, warp tile 32x64).
// Double-buffered smem; permuted layout; LDS.64 fragment loads.
// Requires M%128==0, N%128==0, K%32==0 (true for all shapes here).
// ===========================================================================
#define GBK  32
#define GSTR 36                       // 32 + 4 pad (words)
#define GEMM_SMEM (18432 * 4)         // 2 bufs * (A 128*36 + B 128*36) words

__global__ __launch_bounds__(256, 1)
void gemm_mma(const float* __restrict__ A, const float* __restrict__ B,
              const float* __restrict__ bias, float* __restrict__ C,
              int N, int K)
{
    extern __shared__ uint32_t dsm[];
    const int tid  = threadIdx.x;
    const int lane = tid & 31, wid = tid >> 5;
    const int g = lane >> 2, t = lane & 3;
    const int bm = blockIdx.y * 128, bn = blockIdx.x * 128;
    const int wm = (wid & 3) * 32, wn = (wid >> 2) * 64;

    // LDG mapping
    const int ar = tid >> 1, ah = (tid & 1) * 16;   // A: row ar, cols ah..ah+15
    const int bk = tid >> 3, bj = tid & 7;          // B: row bk, float4 slots bj+8i
    const float* Aq = A + (size_t)(bm + ar) * K + ah;
    const float* Bq = B + (size_t)bk * N + bn + bj * 4;

    float acc[2][8][4];
#pragma unroll
    for (int mt = 0; mt < 2; mt++)
#pragma unroll
        for (int nt = 0; nt < 8; nt++)
#pragma unroll
            for (int r = 0; r < 4; r++) acc[mt][nt][r] = 0.0f;

    float4 a_ld[4], b_ld[4];

#define GEMM_LDG(kt) do {                                                     \
    _Pragma("unroll")                                                         \
    for (int i = 0; i < 4; i++) {                                             \
        a_ld[i] = *(const float4*)(Aq + (size_t)(kt) * GBK + i * 4);          \
        b_ld[i] = *(const float4*)(Bq + (size_t)(kt) * GBK * N + 32 * i);     \
    } } while (0)

#define GEMM_STS(buf) do {                                                    \
    uint32_t* as_ = dsm + (buf) * 9216;                                       \
    uint32_t* bs_ = as_ + 4608;                                               \
    _Pragma("unroll")                                                         \
    for (int i = 0; i < 4; i++) {                                             \
        const float av_[4] = {a_ld[i].x, a_ld[i].y, a_ld[i].z, a_ld[i].w};    \
        const float bv_[4] = {b_ld[i].x, b_ld[i].y, b_ld[i].z, b_ld[i].w};    \
        const int n0_ = (bj + 8 * i) * 4;                                     \
        _Pragma("unroll")                                                     \
        for (int e = 0; e < 4; e++) {                                         \
            as_[ar * GSTR + pcol(ah + i * 4 + e)] = f2tf(av_[e]);             \
            bs_[(n0_ + e) * GSTR + pcol(bk)]      = f2tf(bv_[e]);             \
        }                                                                     \
    } } while (0)

    const int NT = K / GBK;
    GEMM_LDG(0);
    GEMM_STS(0);

    for (int kt = 0; kt < NT; kt++) {
        __syncthreads();
        if (kt + 1 < NT) GEMM_LDG(kt + 1);

        const uint32_t* as = dsm + (kt & 1) * 9216;
        const uint32_t* bs = as + 4608;
#pragma unroll
        for (int ks = 0; ks < 4; ks++) {
            uint32_t af[2][4], bf[8][2];
#pragma unroll
            for (int mt = 0; mt < 2; mt++) {
                const int r0 = wm + mt * 16 + g;
                uint2 lo = *(const uint2*)&as[r0 * GSTR + ks * 8 + 2 * t];
                uint2 hi = *(const uint2*)&as[(r0 + 8) * GSTR + ks * 8 + 2 * t];
                af[mt][0] = lo.x; af[mt][1] = hi.x; af[mt][2] = lo.y; af[mt][3] = hi.y;
            }
#pragma unroll
            for (int nt = 0; nt < 8; nt++) {
                uint2 bb = *(const uint2*)&bs[(wn + nt * 8 + g) * GSTR + ks * 8 + 2 * t];
                bf[nt][0] = bb.x; bf[nt][1] = bb.y;
            }
#pragma unroll
            for (int mt = 0; mt < 2; mt++)
#pragma unroll
                for (int nt = 0; nt < 8; nt++)
                    mma_tf32(acc[mt][nt], af[mt], bf[nt]);
        }
        if (kt + 1 < NT) GEMM_STS((kt + 1) & 1);
    }

    // epilogue: bias + float2 stores
#pragma unroll
    for (int mt = 0; mt < 2; mt++)
#pragma unroll
        for (int rr = 0; rr < 2; rr++) {
            const int row = bm + wm + mt * 16 + g + rr * 8;
            float* Cr = C + (size_t)row * N;
#pragma unroll
            for (int nt = 0; nt < 8; nt++) {
                const int col = bn + wn + nt * 8 + 2 * t;
                float2 bb = *(const float2*)(bias + col);
                float2 o;
                o.x = acc[mt][nt][rr * 2 + 0] + bb.x;
                o.y = acc[mt][nt][rr * 2 + 1] + bb.y;
                *(float2*)(Cr + col) = o;
            }
        }
#undef GEMM_LDG
#undef GEMM_STS
}

// ===========================================================================
// Flash attention, tf32 mma for both S=Q@K^T and O+=P@V. head_dim=64.
// Block = (b, h, 128 q-rows); 8 warps, warp = 16 q-rows (one m16 tile).
// K-tile = 64 keys/iter. Online softmax in C-fragment layout (quad shfl).
// P converted C-frag -> A-frag via per-warp-private smem (syncwarp only).
// smem words: Qs 9216 | Ks 4608 | Vs 4608 | Ps 9216  (stride 72)
// ===========================================================================
#define ASTRD 72
#define ATT_SMEM (27648 * 4)

__global__ __launch_bounds__(256, 2)
void attn_mma(const float* __restrict__ qkv, float* __restrict__ outp)
{
    extern __shared__ uint32_t dsm[];
    uint32_t* Qs = dsm;
    uint32_t* Ks = dsm + 9216;
    uint32_t* Vs = dsm + 13824;
    uint32_t* Ps = dsm + 18432;

    const int tid = threadIdx.x, lane = tid & 31, w = tid >> 5;
    const int g = lane >> 2, t = lane & 3;
    const int qt = blockIdx.x & 15;
    const int h  = (blockIdx.x >> 4) % HEADS;
    const int b  = blockIdx.x / (16 * HEADS);
    const int q0 = qt * 128;

    // ---- Q fill: scaled by d^-0.5, tf32, permuted layout ----
    {
        const int row = tid >> 1, half = (tid & 1) * 32;
        const float* qp = qkv + (size_t)(b * NN + q0 + row) * (3 * DIMC) + h * HD + half;
#pragma unroll
        for (int i = 0; i < 8; i++) {
            float4 v = *(const float4*)(qp + i * 4);
            const float vv[4] = {v.x, v.y, v.z, v.w};
#pragma unroll
            for (int e = 0; e < 4; e++)
                Qs[row * ASTRD + pcol(half + i * 4 + e)] = f2tf(vv[e] * 0.125f);
        }
    }

    float o[8][4];
#pragma unroll
    for (int nt = 0; nt < 8; nt++)
#pragma unroll
        for (int r = 0; r < 4; r++) o[nt][r] = 0.0f;
    float m0 = -CUDART_INF_F, m1 = -CUDART_INF_F, l0 = 0.0f, l1 = 0.0f;

    const int r0 = 16 * w + g;
    const int key = tid >> 2, c4 = tid & 3;
    const float* kvbase = qkv + (size_t)(b * NN + key) * (3 * DIMC) + h * HD;

    for (int kt = 0; kt < NN / 64; kt++) {
        // prefetch K/V tile (overlaps previous iter's compute)
        float4 kf[4], vf[4];
        const float* kp = kvbase + (size_t)(kt * 64) * (3 * DIMC) + DIMC;
        const float* vp = kp + DIMC;
#pragma unroll
        for (int i = 0; i < 4; i++) {
            kf[i] = *(const float4*)(kp + (c4 + 4 * i) * 4);
            vf[i] = *(const float4*)(vp + (c4 + 4 * i) * 4);
        }
        __syncthreads();   // previous iteration's Ks/Vs reads complete
#pragma unroll
        for (int i = 0; i < 4; i++) {
            const float kv_[4] = {kf[i].x, kf[i].y, kf[i].z, kf[i].w};
            const float vv_[4] = {vf[i].x, vf[i].y, vf[i].z, vf[i].w};
#pragma unroll
            for (int e = 0; e < 4; e++) {
                const int d = (c4 + 4 * i) * 4 + e;
                Ks[key * ASTRD + pcol(d)] = f2tf(kv_[e]);      // K: [key][d']
                Vs[d * ASTRD + pcol(key)] = f2tf(vv_[e]);      // V^T: [d][key']
            }
        }
        __syncthreads();

        // ---- S = Q @ K^T (n = keys, k = d) ----
        float s[8][4];
#pragma unroll
        for (int nt = 0; nt < 8; nt++)
#pragma unroll
            for (int r = 0; r < 4; r++) s[nt][r] = 0.0f;

#pragma unroll
        for (int ks = 0; ks < 8; ks++) {
            uint2 alo = *(const uint2*)&Qs[r0 * ASTRD + ks * 8 + 2 * t];
            uint2 ahi = *(const uint2*)&Qs[(r0 + 8) * ASTRD + ks * 8 + 2 * t];
            uint32_t a[4] = {alo.x, ahi.x, alo.y, ahi.y};
#pragma unroll
            for (int nt = 0; nt < 8; nt++) {
                uint2 bb = *(const uint2*)&Ks[(nt * 8 + g) * ASTRD + ks * 8 + 2 * t];
                uint32_t bf2[2] = {bb.x, bb.y};
                mma_tf32(s[nt], a, bf2);
            }
        }

        // ---- online softmax (rows g and g+8; quad = same row) ----
        float mx0 = -CUDART_INF_F, mx1 = -CUDART_INF_F;
#pragma unroll
        for (int nt = 0; nt < 8; nt++) {
            mx0 = fmaxf(mx0, fmaxf(s[nt][0], s[nt][1]));
            mx1 = fmaxf(mx1, fmaxf(s[nt][2], s[nt][3]));
        }
        mx0 = fmaxf(mx0, __shfl_xor_sync(0xffffffffu, mx0, 1));
        mx0 = fmaxf(mx0, __shfl_xor_sync(0xffffffffu, mx0, 2));
        mx1 = fmaxf(mx1, __shfl_xor_sync(0xffffffffu, mx1, 1));
        mx1 = fmaxf(mx1, __shfl_xor_sync(0xffffffffu, mx1, 2));
        const float nm0 = fmaxf(m0, mx0), nm1 = fmaxf(m1, mx1);
        const float cr0 = __expf(m0 - nm0), cr1 = __expf(m1 - nm1);
        float rs0 = 0.0f, rs1 = 0.0f;
#pragma unroll
        for (int nt = 0; nt < 8; nt++) {
            s[nt][0] = __expf(s[nt][0] - nm0);
            s[nt][1] = __expf(s[nt][1] - nm0);
            s[nt][2] = __expf(s[nt][2] - nm1);
            s[nt][3] = __expf(s[nt][3] - nm1);
            rs0 += s[nt][0] + s[nt][1];
            rs1 += s[nt][2] + s[nt][3];
        }
        rs0 += __shfl_xor_sync(0xffffffffu, rs0, 1);
        rs0 += __shfl_xor_sync(0xffffffffu, rs0, 2);
        rs1 += __shfl_xor_sync(0xffffffffu, rs1, 1);
        rs1 += __shfl_xor_sync(0xffffffffu, rs1, 2);
        l0 = l0 * cr0 + rs0;  m0 = nm0;
        l1 = l1 * cr1 + rs1;  m1 = nm1;
#pragma unroll
        for (int nt = 0; nt < 8; nt++) {
            o[nt][0] *= cr0; o[nt][1] *= cr0;
            o[nt][2] *= cr1; o[nt][3] *= cr1;
        }

        // ---- P: C-frag -> smem (per-warp private rows) ----
#pragma unroll
        for (int nt = 0; nt < 8; nt++) {
            const int j0 = nt * 8 + 2 * t;
            Ps[r0 * ASTRD + pcol(j0)]           = f2tf(s[nt][0]);
            Ps[r0 * ASTRD + pcol(j0 + 1)]       = f2tf(s[nt][1]);
            Ps[(r0 + 8) * ASTRD + pcol(j0)]     = f2tf(s[nt][2]);
            Ps[(r0 + 8) * ASTRD + pcol(j0 + 1)] = f2tf(s[nt][3]);
        }
        __syncwarp();

        // ---- O += P @ V (n = d, k = keys) ----
#pragma unroll
        for (int ks = 0; ks < 8; ks++) {
            uint2 plo = *(const uint2*)&Ps[r0 * ASTRD + ks * 8 + 2 * t];
            uint2 phi = *(const uint2*)&Ps[(r0 + 8) * ASTRD + ks * 8 + 2 * t];
            uint32_t a[4] = {plo.x, phi.x, plo.y, phi.y};
#pragma unroll
            for (int nt = 0; nt < 8; nt++) {
                uint2 bb = *(const uint2*)&Vs[(nt * 8 + g) * ASTRD + ks * 8 + 2 * t];
                uint32_t bf2[2] = {bb.x, bb.y};
                mma_tf32(o[nt], a, bf2);
            }
        }
        __syncwarp();
    }

    // ---- epilogue: normalize, store to [B*N, 768] ----
    const float inv0 = 1.0f / l0, inv1 = 1.0f / l1;
    const int grow = b * NN + q0 + 16 * w + g;
    float* or0 = outp + (size_t)grow * DIMC + h * HD;
    float* or1 = outp + (size_t)(grow + 8) * DIMC + h * HD;
#pragma unroll
    for (int nt = 0; nt < 8; nt++) {
        const int col = nt * 8 + 2 * t;
        float2 v0; v0.x = o[nt][0] * inv0; v0.y = o[nt][1] * inv0;
        float2 v1; v1.x = o[nt][2] * inv1; v1.y = o[nt][3] * inv1;
        *(float2*)(or0 + col) = v0;
        *(float2*)(or1 + col) = v1;
    }
}

// ---------------------------------------------------------------------------
extern "C" void kernel_launch(void* const* d_in, const int* in_sizes, int n_in,
                              void* d_out, int out_size)
{
    const float* x      = (const float*)d_in[0];
    const float* w_qkv  = (const float*)d_in[1];
    const float* b_qkv  = (const float*)d_in[2];
    const float* w_proj = (const float*)d_in[3];
    const float* b_proj = (const float*)d_in[4];
    float* out = (float*)d_out;

    float *qkv_s = nullptr, *att_s = nullptr;
    cudaGetSymbolAddress((void**)&qkv_s, g_qkv);
    cudaGetSymbolAddress((void**)&att_s, g_att);

    cudaFuncSetAttribute(gemm_mma, cudaFuncAttributeMaxDynamicSharedMemorySize, GEMM_SMEM);
    cudaFuncSetAttribute(attn_mma, cudaFuncAttributeMaxDynamicSharedMemorySize, ATT_SMEM);

    // 1) QKV GEMM: [8192,768] @ [768,2304] + bias
    {
        dim3 grid((3 * DIMC) / 128, MTOK / 128);
        gemm_mma<<<grid, 256, GEMM_SMEM>>>(x, w_qkv, b_qkv, qkv_s, 3 * DIMC, DIMC);
    }

    // 2) Flash attention (tf32 mma): 4*12*16 = 768 blocks
    attn_mma<<<BB * HEADS * 16, 256, ATT_SMEM>>>(qkv_s, att_s);

    // 3) Projection GEMM: [8192,768] @ [768,768] + bias
    {
        dim3 grid(DIMC / 128, MTOK / 128);
        gemm_mma<<<grid, 256, GEMM_SMEM>>>(att_s, w_proj, b_proj, out, DIMC, DIMC);
    }
}

// round 6
// speedup vs baseline: 2.2362x; 1.0001x over previous
#include <cuda_runtime.h>
#include <math_constants.h>
#include <cstdint>

#define BB    4
#define NN    2048
#define DIMC  768
#define HEADS 12
#define HD    64
#define MTOK  (BB * NN)   /* 8192 tokens */

// Scratch (allocation-free rule: __device__ globals)
__device__ float g_qkv[(size_t)MTOK * 3 * DIMC];   // [8192, 2304]
__device__ float g_att[(size_t)MTOK * DIMC];       // [8192, 768]

// ---------------------------------------------------------------------------
// tf32 helpers (sm_80+ PTX only — NO 'a'-gated instructions)
// ---------------------------------------------------------------------------
__device__ __forceinline__ uint32_t f2tf(float x) {
    uint32_t r;
    asm("cvt.rna.tf32.f32 %0, %1;" : "=r"(r) : "f"(x));
    return r;
}

// D += A @ B ; m16n8k8 tf32, fp32 accumulate.
// A frag: a0=(g,t) a1=(g+8,t) a2=(g,t+4) a3=(g+8,t+4); g=lane>>2, t=lane&3
// B frag: b0=(k=t, n=g) b1=(k=t+4, n=g)
// C frag: c0=(g,2t) c1=(g,2t+1) c2=(g+8,2t) c3=(g+8,2t+1)
__device__ __forceinline__ void mma_tf32(float* d, const uint32_t* a, const uint32_t* b) {
    asm volatile(
        "mma.sync.aligned.m16n8k8.row.col.f32.tf32.tf32.f32 "
        "{%0,%1,%2,%3}, {%4,%5,%6,%7}, {%8,%9}, {%0,%1,%2,%3};"
        : "+f"(d[0]), "+f"(d[1]), "+f"(d[2]), "+f"(d[3])
        : "r"(a[0]), "r"(a[1]), "r"(a[2]), "r"(a[3]), "r"(b[0]), "r"(b[1]));
}

// Within-8 column permutation so that (c, c+4) land adjacent -> LDS.64 frags.
// p(j) = 2*(j&3) + (j>>2), applied per 8-wide k-block.
__device__ __forceinline__ int pcol(int c) {
    return (c & ~7) + ((c & 3) << 1) + ((c >> 2) & 1);
}

// ===========================================================================
// GEMM: C[M,N] = A[M,K] @ B[K,N] + bias[N]   (tf32 mma.sync)
// 128x128 tile, BK=32, 256 threads (8 warps, 4x2 layout, warp tile 32x64).
// Double-buffered smem; permuted layout; LDS.64 fragment loads.
// Requires M%128==0, N%128==0, K%32==0 (true for all shapes here).
// ===========================================================================
#define GBK  32
#define GSTR 36                       // 32 + 4 pad (words)
#define GEMM_SMEM (18432 * 4)         // 2 bufs * (A 128*36 + B 128*36) words

__global__ __launch_bounds__(256, 1)
void gemm_mma(const float* __restrict__ A, const float* __restrict__ B,
              const float* __restrict__ bias, float* __restrict__ C,
              int N, int K)
{
    extern __shared__ uint32_t dsm[];
    const int tid  = threadIdx.x;
    const int lane = tid & 31, wid = tid >> 5;
    const int g = lane >> 2, t = lane & 3;
    const int bm = blockIdx.y * 128, bn = blockIdx.x * 128;
    const int wm = (wid & 3) * 32, wn = (wid >> 2) * 64;

    // LDG mapping
    const int ar = tid >> 1, ah = (tid & 1) * 16;   // A: row ar, cols ah..ah+15
    const int bk = tid >> 3, bj = tid & 7;          // B: row bk, float4 slots bj+8i
    const float* Aq = A + (size_t)(bm + ar) * K + ah;
    const float* Bq = B + (size_t)bk * N + bn + bj * 4;

    float acc[2][8][4];
#pragma unroll
    for (int mt = 0; mt < 2; mt++)
#pragma unroll
        for (int nt = 0; nt < 8; nt++)
#pragma unroll
            for (int r = 0; r < 4; r++) acc[mt][nt][r] = 0.0f;

    float4 a_ld[4], b_ld[4];

#define GEMM_LDG(kt) do {                                                     \
    _Pragma("unroll")                                                         \
    for (int i = 0; i < 4; i++) {                                             \
        a_ld[i] = *(const float4*)(Aq + (size_t)(kt) * GBK + i * 4);          \
        b_ld[i] = *(const float4*)(Bq + (size_t)(kt) * GBK * N + 32 * i);     \
    } } while (0)

#define GEMM_STS(buf) do {                                                    \
    uint32_t* as_ = dsm + (buf) * 9216;                                       \
    uint32_t* bs_ = as_ + 4608;                                               \
    _Pragma("unroll")                                                         \
    for (int i = 0; i < 4; i++) {                                             \
        const float av_[4] = {a_ld[i].x, a_ld[i].y, a_ld[i].z, a_ld[i].w};    \
        const float bv_[4] = {b_ld[i].x, b_ld[i].y, b_ld[i].z, b_ld[i].w};    \
        const int n0_ = (bj + 8 * i) * 4;                                     \
        _Pragma("unroll")                                                     \
        for (int e = 0; e < 4; e++) {                                         \
            as_[ar * GSTR + pcol(ah + i * 4 + e)] = f2tf(av_[e]);             \
            bs_[(n0_ + e) * GSTR + pcol(bk)]      = f2tf(bv_[e]);             \
        }                                                                     \
    } } while (0)

    const int NT = K / GBK;
    GEMM_LDG(0);
    GEMM_STS(0);

    for (int kt = 0; kt < NT; kt++) {
        __syncthreads();
        if (kt + 1 < NT) GEMM_LDG(kt + 1);

        const uint32_t* as = dsm + (kt & 1) * 9216;
        const uint32_t* bs = as + 4608;
#pragma unroll
        for (int ks = 0; ks < 4; ks++) {
            uint32_t af[2][4], bf[8][2];
#pragma unroll
            for (int mt = 0; mt < 2; mt++) {
                const int r0 = wm + mt * 16 + g;
                uint2 lo = *(const uint2*)&as[r0 * GSTR + ks * 8 + 2 * t];
                uint2 hi = *(const uint2*)&as[(r0 + 8) * GSTR + ks * 8 + 2 * t];
                af[mt][0] = lo.x; af[mt][1] = hi.x; af[mt][2] = lo.y; af[mt][3] = hi.y;
            }
#pragma unroll
            for (int nt = 0; nt < 8; nt++) {
                uint2 bb = *(const uint2*)&bs[(wn + nt * 8 + g) * GSTR + ks * 8 + 2 * t];
                bf[nt][0] = bb.x; bf[nt][1] = bb.y;
            }
#pragma unroll
            for (int mt = 0; mt < 2; mt++)
#pragma unroll
                for (int nt = 0; nt < 8; nt++)
                    mma_tf32(acc[mt][nt], af[mt], bf[nt]);
        }
        if (kt + 1 < NT) GEMM_STS((kt + 1) & 1);
    }

    // epilogue: bias + float2 stores
#pragma unroll
    for (int mt = 0; mt < 2; mt++)
#pragma unroll
        for (int rr = 0; rr < 2; rr++) {
            const int row = bm + wm + mt * 16 + g + rr * 8;
            float* Cr = C + (size_t)row * N;
#pragma unroll
            for (int nt = 0; nt < 8; nt++) {
                const int col = bn + wn + nt * 8 + 2 * t;
                float2 bb = *(const float2*)(bias + col);
                float2 o;
                o.x = acc[mt][nt][rr * 2 + 0] + bb.x;
                o.y = acc[mt][nt][rr * 2 + 1] + bb.y;
                *(float2*)(Cr + col) = o;
            }
        }
#undef GEMM_LDG
#undef GEMM_STS
}

// ===========================================================================
// Flash attention, tf32 mma for both S=Q@K^T and O+=P@V. head_dim=64.
// Block = (b, h, 128 q-rows); 8 warps, warp = 16 q-rows (one m16 tile).
// K-tile = 64 keys/iter. Online softmax in C-fragment layout (quad shfl).
// P converted C-frag -> A-frag via per-warp-private smem (syncwarp only).
// smem words: Qs 9216 | Ks 4608 | Vs 4608 | Ps 9216  (stride 72)
// ===========================================================================
#define ASTRD 72
#define ATT_SMEM (27648 * 4)

__global__ __launch_bounds__(256, 2)
void attn_mma(const float* __restrict__ qkv, float* __restrict__ outp)
{
    extern __shared__ uint32_t dsm[];
    uint32_t* Qs = dsm;
    uint32_t* Ks = dsm + 9216;
    uint32_t* Vs = dsm + 13824;
    uint32_t* Ps = dsm + 18432;

    const int tid = threadIdx.x, lane = tid & 31, w = tid >> 5;
    const int g = lane >> 2, t = lane & 3;
    const int qt = blockIdx.x & 15;
    const int h  = (blockIdx.x >> 4) % HEADS;
    const int b  = blockIdx.x / (16 * HEADS);
    const int q0 = qt * 128;

    // ---- Q fill: scaled by d^-0.5, tf32, permuted layout ----
    {
        const int row = tid >> 1, half = (tid & 1) * 32;
        const float* qp = qkv + (size_t)(b * NN + q0 + row) * (3 * DIMC) + h * HD + half;
#pragma unroll
        for (int i = 0; i < 8; i++) {
            float4 v = *(const float4*)(qp + i * 4);
            const float vv[4] = {v.x, v.y, v.z, v.w};
#pragma unroll
            for (int e = 0; e < 4; e++)
                Qs[row * ASTRD + pcol(half + i * 4 + e)] = f2tf(vv[e] * 0.125f);
        }
    }

    float o[8][4];
#pragma unroll
    for (int nt = 0; nt < 8; nt++)
#pragma unroll
        for (int r = 0; r < 4; r++) o[nt][r] = 0.0f;
    float m0 = -CUDART_INF_F, m1 = -CUDART_INF_F, l0 = 0.0f, l1 = 0.0f;

    const int r0 = 16 * w + g;
    const int key = tid >> 2, c4 = tid & 3;
    const float* kvbase = qkv + (size_t)(b * NN + key) * (3 * DIMC) + h * HD;

    for (int kt = 0; kt < NN / 64; kt++) {
        // prefetch K/V tile (overlaps previous iter's compute)
        float4 kf[4], vf[4];
        const float* kp = kvbase + (size_t)(kt * 64) * (3 * DIMC) + DIMC;
        const float* vp = kp + DIMC;
#pragma unroll
        for (int i = 0; i < 4; i++) {
            kf[i] = *(const float4*)(kp + (c4 + 4 * i) * 4);
            vf[i] = *(const float4*)(vp + (c4 + 4 * i) * 4);
        }
        __syncthreads();   // previous iteration's Ks/Vs reads complete
#pragma unroll
        for (int i = 0; i < 4; i++) {
            const float kv_[4] = {kf[i].x, kf[i].y, kf[i].z, kf[i].w};
            const float vv_[4] = {vf[i].x, vf[i].y, vf[i].z, vf[i].w};
#pragma unroll
            for (int e = 0; e < 4; e++) {
                const int d = (c4 + 4 * i) * 4 + e;
                Ks[key * ASTRD + pcol(d)] = f2tf(kv_[e]);      // K: [key][d']
                Vs[d * ASTRD + pcol(key)] = f2tf(vv_[e]);      // V^T: [d][key']
            }
        }
        __syncthreads();

        // ---- S = Q @ K^T (n = keys, k = d) ----
        float s[8][4];
#pragma unroll
        for (int nt = 0; nt < 8; nt++)
#pragma unroll
            for (int r = 0; r < 4; r++) s[nt][r] = 0.0f;

#pragma unroll
        for (int ks = 0; ks < 8; ks++) {
            uint2 alo = *(const uint2*)&Qs[r0 * ASTRD + ks * 8 + 2 * t];
            uint2 ahi = *(const uint2*)&Qs[(r0 + 8) * ASTRD + ks * 8 + 2 * t];
            uint32_t a[4] = {alo.x, ahi.x, alo.y, ahi.y};
#pragma unroll
            for (int nt = 0; nt < 8; nt++) {
                uint2 bb = *(const uint2*)&Ks[(nt * 8 + g) * ASTRD + ks * 8 + 2 * t];
                uint32_t bf2[2] = {bb.x, bb.y};
                mma_tf32(s[nt], a, bf2);
            }
        }

        // ---- online softmax (rows g and g+8; quad = same row) ----
        float mx0 = -CUDART_INF_F, mx1 = -CUDART_INF_F;
#pragma unroll
        for (int nt = 0; nt < 8; nt++) {
            mx0 = fmaxf(mx0, fmaxf(s[nt][0], s[nt][1]));
            mx1 = fmaxf(mx1, fmaxf(s[nt][2], s[nt][3]));
        }
        mx0 = fmaxf(mx0, __shfl_xor_sync(0xffffffffu, mx0, 1));
        mx0 = fmaxf(mx0, __shfl_xor_sync(0xffffffffu, mx0, 2));
        mx1 = fmaxf(mx1, __shfl_xor_sync(0xffffffffu, mx1, 1));
        mx1 = fmaxf(mx1, __shfl_xor_sync(0xffffffffu, mx1, 2));
        const float nm0 = fmaxf(m0, mx0), nm1 = fmaxf(m1, mx1);
        const float cr0 = __expf(m0 - nm0), cr1 = __expf(m1 - nm1);
        float rs0 = 0.0f, rs1 = 0.0f;
#pragma unroll
        for (int nt = 0; nt < 8; nt++) {
            s[nt][0] = __expf(s[nt][0] - nm0);
            s[nt][1] = __expf(s[nt][1] - nm0);
            s[nt][2] = __expf(s[nt][2] - nm1);
            s[nt][3] = __expf(s[nt][3] - nm1);
            rs0 += s[nt][0] + s[nt][1];
            rs1 += s[nt][2] + s[nt][3];
        }
        rs0 += __shfl_xor_sync(0xffffffffu, rs0, 1);
        rs0 += __shfl_xor_sync(0xffffffffu, rs0, 2);
        rs1 += __shfl_xor_sync(0xffffffffu, rs1, 1);
        rs1 += __shfl_xor_sync(0xffffffffu, rs1, 2);
        l0 = l0 * cr0 + rs0;  m0 = nm0;
        l1 = l1 * cr1 + rs1;  m1 = nm1;
#pragma unroll
        for (int nt = 0; nt < 8; nt++) {
            o[nt][0] *= cr0; o[nt][1] *= cr0;
            o[nt][2] *= cr1; o[nt][3] *= cr1;
        }

        // ---- P: C-frag -> smem (per-warp private rows) ----
#pragma unroll
        for (int nt = 0; nt < 8; nt++) {
            const int j0 = nt * 8 + 2 * t;
            Ps[r0 * ASTRD + pcol(j0)]           = f2tf(s[nt][0]);
            Ps[r0 * ASTRD + pcol(j0 + 1)]       = f2tf(s[nt][1]);
            Ps[(r0 + 8) * ASTRD + pcol(j0)]     = f2tf(s[nt][2]);
            Ps[(r0 + 8) * ASTRD + pcol(j0 + 1)] = f2tf(s[nt][3]);
        }
        __syncwarp();

        // ---- O += P @ V (n = d, k = keys) ----
#pragma unroll
        for (int ks = 0; ks < 8; ks++) {
            uint2 plo = *(const uint2*)&Ps[r0 * ASTRD + ks * 8 + 2 * t];
            uint2 phi = *(const uint2*)&Ps[(r0 + 8) * ASTRD + ks * 8 + 2 * t];
            uint32_t a[4] = {plo.x, phi.x, plo.y, phi.y};
#pragma unroll
            for (int nt = 0; nt < 8; nt++) {
                uint2 bb = *(const uint2*)&Vs[(nt * 8 + g) * ASTRD + ks * 8 + 2 * t];
                uint32_t bf2[2] = {bb.x, bb.y};
                mma_tf32(o[nt], a, bf2);
            }
        }
        __syncwarp();
    }

    // ---- epilogue: normalize, store to [B*N, 768] ----
    const float inv0 = 1.0f / l0, inv1 = 1.0f / l1;
    const int grow = b * NN + q0 + 16 * w + g;
    float* or0 = outp + (size_t)grow * DIMC + h * HD;
    float* or1 = outp + (size_t)(grow + 8) * DIMC + h * HD;
#pragma unroll
    for (int nt = 0; nt < 8; nt++) {
        const int col = nt * 8 + 2 * t;
        float2 v0; v0.x = o[nt][0] * inv0; v0.y = o[nt][1] * inv0;
        float2 v1; v1.x = o[nt][2] * inv1; v1.y = o[nt][3] * inv1;
        *(float2*)(or0 + col) = v0;
        *(float2*)(or1 + col) = v1;
    }
}

// ---------------------------------------------------------------------------
extern "C" void kernel_launch(void* const* d_in, const int* in_sizes, int n_in,
                              void* d_out, int out_size)
{
    const float* x      = (const float*)d_in[0];
    const float* w_qkv  = (const float*)d_in[1];
    const float* b_qkv  = (const float*)d_in[2];
    const float* w_proj = (const float*)d_in[3];
    const float* b_proj = (const float*)d_in[4];
    float* out = (float*)d_out;

    float *qkv_s = nullptr, *att_s = nullptr;
    cudaGetSymbolAddress((void**)&qkv_s, g_qkv);
    cudaGetSymbolAddress((void**)&att_s, g_att);

    cudaFuncSetAttribute(gemm_mma, cudaFuncAttributeMaxDynamicSharedMemorySize, GEMM_SMEM);
    cudaFuncSetAttribute(attn_mma, cudaFuncAttributeMaxDynamicSharedMemorySize, ATT_SMEM);

    // 1) QKV GEMM: [8192,768] @ [768,2304] + bias
    {
        dim3 grid((3 * DIMC) / 128, MTOK / 128);
        gemm_mma<<<grid, 256, GEMM_SMEM>>>(x, w_qkv, b_qkv, qkv_s, 3 * DIMC, DIMC);
    }

    // 2) Flash attention (tf32 mma): 4*12*16 = 768 blocks
    attn_mma<<<BB * HEADS * 16, 256, ATT_SMEM>>>(qkv_s, att_s);

    // 3) Projection GEMM: [8192,768] @ [768,768] + bias
    {
        dim3 grid(DIMC / 128, MTOK / 128);
        gemm_mma<<<grid, 256, GEMM_SMEM>>>(att_s, w_proj, b_proj, out, DIMC, DIMC);
    }
}